// round 1
// baseline (speedup 1.0000x reference)
#include <cuda_runtime.h>
#include <cuda_bf16.h>
#include <cstdint>

// ---------------- problem constants ----------------
#define NN      50000
#define EE      800000
#define ET      (EE + NN)        // edges incl. self loops = 850000
#define IN_DIM  256
#define HID     32
#define HEADS   4
#define OUT_DIM 40
#define F1      (HEADS * HID)    // 128
#define F2      (HEADS * OUT_DIM) // 160
#define SLOPE   0.2f

// ---------------- scratch (static device memory; no allocs) ----------------
__device__ float    g_xl1[(size_t)NN * F1];
__device__ float    g_xr1[(size_t)NN * F1];
__device__ float    g_agg1[(size_t)NN * F1];
__device__ float    g_h[(size_t)NN * F1];
__device__ float    g_xl2[(size_t)NN * F2];
__device__ float    g_xr2[(size_t)NN * F2];
__device__ float    g_agg2[(size_t)NN * F2];
__device__ float    g_e1[(size_t)ET * 4];
__device__ float    g_a1[(size_t)ET * 4];
__device__ float    g_e2[(size_t)ET * 4];
__device__ float    g_a2[(size_t)ET * 4];
__device__ unsigned g_m1[(size_t)NN * 4];
__device__ float    g_s1[(size_t)NN * 4];
__device__ unsigned g_m2[(size_t)NN * 4];
__device__ float    g_s2[(size_t)NN * 4];

// ordered-int encoding for float atomicMax
__device__ __forceinline__ unsigned ordf(float f) {
    unsigned u = __float_as_uint(f);
    return (u & 0x80000000u) ? ~u : (u | 0x80000000u);
}
__device__ __forceinline__ float deordf(unsigned o) {
    return __uint_as_float((o & 0x80000000u) ? (o ^ 0x80000000u) : ~o);
}

// ---------------- zero-init ----------------
__global__ void zero_kernel(float* agg1, float* agg2,
                            unsigned* m1, float* s1, unsigned* m2, float* s2)
{
    size_t total = (size_t)NN * F1 + (size_t)NN * F2 + 4ull * NN * 4;
    for (size_t i = (size_t)blockIdx.x * blockDim.x + threadIdx.x;
         i < total; i += (size_t)gridDim.x * blockDim.x) {
        if (i < (size_t)NN * F1) { agg1[i] = 0.f; continue; }
        size_t j = i - (size_t)NN * F1;
        if (j < (size_t)NN * F2) { agg2[j] = 0.f; continue; }
        size_t k = j - (size_t)NN * F2;
        size_t which = k / ((size_t)NN * 4);
        size_t off   = k % ((size_t)NN * 4);
        if (which == 0)      m1[off] = 0u;
        else if (which == 1) s1[off] = 0.f;
        else if (which == 2) m2[off] = 0u;
        else                 s2[off] = 0.f;
    }
}

// ---------------- SGEMM: C[M,Ncol] = A[M,K] @ B[K,Ncol] + bias ----------------
// 64x64 tile, 256 threads, 4x4 per thread. K must be a multiple of 16.
__global__ void sgemm_bias_kernel(const float* __restrict__ A,
                                  const float* __restrict__ B,
                                  const float* __restrict__ bias,
                                  float* __restrict__ C,
                                  int M, int K, int Ncol)
{
    const int BM = 64, BN = 64, BK = 16;
    __shared__ float As[BK][BM];
    __shared__ float Bs[BK][BN];
    int tid = threadIdx.x;
    int tx = tid & 15, ty = tid >> 4;
    int rowBase = blockIdx.y * BM;
    int colBase = blockIdx.x * BN;

    float acc[4][4] = {};

    for (int k0 = 0; k0 < K; k0 += BK) {
        // A tile (transposed into As)
        {
            int r  = tid >> 2;
            int kk = (tid & 3) * 4;
            int grow = rowBase + r;
            float4 v = make_float4(0.f, 0.f, 0.f, 0.f);
            if (grow < M)
                v = *(const float4*)(A + (size_t)grow * K + k0 + kk);
            As[kk + 0][r] = v.x; As[kk + 1][r] = v.y;
            As[kk + 2][r] = v.z; As[kk + 3][r] = v.w;
        }
        // B tile
        {
            int kr = tid >> 4;
            int cc = (tid & 15) * 4;
            int gcol = colBase + cc;
            float4 v = make_float4(0.f, 0.f, 0.f, 0.f);
            if (gcol + 3 < Ncol) {
                v = *(const float4*)(B + (size_t)(k0 + kr) * Ncol + gcol);
            } else {
                float t0 = (gcol + 0 < Ncol) ? B[(size_t)(k0 + kr) * Ncol + gcol + 0] : 0.f;
                float t1 = (gcol + 1 < Ncol) ? B[(size_t)(k0 + kr) * Ncol + gcol + 1] : 0.f;
                float t2 = (gcol + 2 < Ncol) ? B[(size_t)(k0 + kr) * Ncol + gcol + 2] : 0.f;
                float t3 = (gcol + 3 < Ncol) ? B[(size_t)(k0 + kr) * Ncol + gcol + 3] : 0.f;
                v = make_float4(t0, t1, t2, t3);
            }
            *(float4*)&Bs[kr][cc] = v;
        }
        __syncthreads();

        #pragma unroll
        for (int k = 0; k < BK; k++) {
            float ra[4], rb[4];
            #pragma unroll
            for (int i = 0; i < 4; i++) ra[i] = As[k][ty * 4 + i];
            #pragma unroll
            for (int j = 0; j < 4; j++) rb[j] = Bs[k][tx * 4 + j];
            #pragma unroll
            for (int i = 0; i < 4; i++)
                #pragma unroll
                for (int j = 0; j < 4; j++)
                    acc[i][j] += ra[i] * rb[j];
        }
        __syncthreads();
    }

    #pragma unroll
    for (int i = 0; i < 4; i++) {
        int grow = rowBase + ty * 4 + i;
        if (grow >= M) continue;
        #pragma unroll
        for (int j = 0; j < 4; j++) {
            int gcol = colBase + tx * 4 + j;
            if (gcol < Ncol)
                C[(size_t)grow * Ncol + gcol] = acc[i][j] + bias[gcol];
        }
    }
}

// ---------------- layer 1 edge logits (warp per edge, 128 feats) ----------------
__global__ void edge_logits1_kernel(const float* __restrict__ xl,
                                    const float* __restrict__ xr,
                                    const int* __restrict__ esrc,
                                    const int* __restrict__ edst,
                                    const float* __restrict__ att,
                                    float* __restrict__ eout,
                                    unsigned* __restrict__ mord)
{
    int warp = (blockIdx.x * blockDim.x + threadIdx.x) >> 5;
    int lane = threadIdx.x & 31;
    if (warp >= ET) return;
    int s, d;
    if (warp < EE) { s = esrc[warp]; d = edst[warp]; }
    else           { s = d = warp - EE; }

    float4 vl = *(const float4*)(xl + (size_t)s * F1 + lane * 4);
    float4 vr = *(const float4*)(xr + (size_t)d * F1 + lane * 4);
    float4 va = *(const float4*)(att + lane * 4);

    float g, sum = 0.f;
    g = vl.x + vr.x; g = g > 0.f ? g : SLOPE * g; sum += g * va.x;
    g = vl.y + vr.y; g = g > 0.f ? g : SLOPE * g; sum += g * va.y;
    g = vl.z + vr.z; g = g > 0.f ? g : SLOPE * g; sum += g * va.z;
    g = vl.w + vr.w; g = g > 0.f ? g : SLOPE * g; sum += g * va.w;

    // reduce within groups of 8 lanes (one head each)
    sum += __shfl_xor_sync(0xffffffffu, sum, 1);
    sum += __shfl_xor_sync(0xffffffffu, sum, 2);
    sum += __shfl_xor_sync(0xffffffffu, sum, 4);

    if ((lane & 7) == 0) {
        int h = lane >> 3;
        eout[(size_t)warp * 4 + h] = sum;
        atomicMax(&mord[d * 4 + h], ordf(sum));
    }
}

// ---------------- layer 2 edge logits (warp per edge, 4 heads x 40) ----------------
__global__ void edge_logits2_kernel(const float* __restrict__ xl,
                                    const float* __restrict__ xr,
                                    const int* __restrict__ esrc,
                                    const int* __restrict__ edst,
                                    const float* __restrict__ att,
                                    float* __restrict__ eout,
                                    unsigned* __restrict__ mord)
{
    int warp = (blockIdx.x * blockDim.x + threadIdx.x) >> 5;
    int lane = threadIdx.x & 31;
    if (warp >= ET) return;
    int s, d;
    if (warp < EE) { s = esrc[warp]; d = edst[warp]; }
    else           { s = d = warp - EE; }

    const float* rl = xl + (size_t)s * F2;
    const float* rr = xr + (size_t)d * F2;

    #pragma unroll
    for (int h = 0; h < HEADS; h++) {
        int base = h * OUT_DIM;
        float partial = 0.f;
        {
            int c = lane; // lane < 32 < 40
            float g = rl[base + c] + rr[base + c];
            g = g > 0.f ? g : SLOPE * g;
            partial += g * att[base + c];
        }
        if (lane < 8) {
            int c = lane + 32;
            float g = rl[base + c] + rr[base + c];
            g = g > 0.f ? g : SLOPE * g;
            partial += g * att[base + c];
        }
        #pragma unroll
        for (int off = 16; off > 0; off >>= 1)
            partial += __shfl_xor_sync(0xffffffffu, partial, off);
        if (lane == 0) {
            eout[(size_t)warp * 4 + h] = partial;
            atomicMax(&mord[d * 4 + h], ordf(partial));
        }
    }
}

// ---------------- exp & segment-sum (generic) ----------------
__global__ void exp_sum_kernel(const float* __restrict__ eout,
                               const unsigned* __restrict__ mord,
                               const int* __restrict__ edst,
                               float* __restrict__ aout,
                               float* __restrict__ ssum)
{
    int idx = blockIdx.x * blockDim.x + threadIdx.x;
    if (idx >= ET * 4) return;
    int e = idx >> 2, h = idx & 3;
    int d = (e < EE) ? edst[e] : e - EE;
    float m = deordf(mord[d * 4 + h]);
    float a = __expf(eout[idx] - m);
    aout[idx] = a;
    atomicAdd(&ssum[d * 4 + h], a);
}

// ---------------- layer 1 aggregation (warp per edge, atomics) ----------------
__global__ void aggregate1_kernel(const float* __restrict__ xl,
                                  const float* __restrict__ aout,
                                  const float* __restrict__ ssum,
                                  const int* __restrict__ esrc,
                                  const int* __restrict__ edst,
                                  float* __restrict__ agg)
{
    int warp = (blockIdx.x * blockDim.x + threadIdx.x) >> 5;
    int lane = threadIdx.x & 31;
    if (warp >= ET) return;
    int s, d;
    if (warp < EE) { s = esrc[warp]; d = edst[warp]; }
    else           { s = d = warp - EE; }

    int h = lane >> 3;
    float coef = aout[(size_t)warp * 4 + h] / (ssum[d * 4 + h] + 1e-16f);
    float4 v = *(const float4*)(xl + (size_t)s * F1 + lane * 4);
    float* o = agg + (size_t)d * F1 + lane * 4;
    atomicAdd(o + 0, coef * v.x);
    atomicAdd(o + 1, coef * v.y);
    atomicAdd(o + 2, coef * v.z);
    atomicAdd(o + 3, coef * v.w);
}

// ---------------- layer 2 aggregation ----------------
__global__ void aggregate2_kernel(const float* __restrict__ xl,
                                  const float* __restrict__ aout,
                                  const float* __restrict__ ssum,
                                  const int* __restrict__ esrc,
                                  const int* __restrict__ edst,
                                  float* __restrict__ agg)
{
    int warp = (blockIdx.x * blockDim.x + threadIdx.x) >> 5;
    int lane = threadIdx.x & 31;
    if (warp >= ET) return;
    int s, d;
    if (warp < EE) { s = esrc[warp]; d = edst[warp]; }
    else           { s = d = warp - EE; }

    float coef[HEADS];
    #pragma unroll
    for (int h = 0; h < HEADS; h++)
        coef[h] = aout[(size_t)warp * 4 + h] / (ssum[d * 4 + h] + 1e-16f);

    const float* rl = xl + (size_t)s * F2;
    float* o = agg + (size_t)d * F2;
    #pragma unroll
    for (int h = 0; h < HEADS; h++) {
        int base = h * OUT_DIM;
        {
            int c = lane;
            atomicAdd(o + base + c, coef[h] * rl[base + c]);
        }
        if (lane < 8) {
            int c = lane + 32;
            atomicAdd(o + base + c, coef[h] * rl[base + c]);
        }
    }
}

// ---------------- finalize layer 1: h = elu(agg + bias1) ----------------
__global__ void finalize1_kernel(const float* __restrict__ agg,
                                 const float* __restrict__ bias,
                                 float* __restrict__ hout)
{
    int idx = blockIdx.x * blockDim.x + threadIdx.x;
    if (idx >= NN * F1) return;
    float v = agg[idx] + bias[idx % F1];
    hout[idx] = v > 0.f ? v : (__expf(v) - 1.f);
}

// ---------------- finalize layer 2: out = mean_h(agg2) + bias2 ----------------
__global__ void finalize2_kernel(const float* __restrict__ agg,
                                 const float* __restrict__ bias,
                                 float* __restrict__ out)
{
    int idx = blockIdx.x * blockDim.x + threadIdx.x;
    if (idx >= NN * OUT_DIM) return;
    int n = idx / OUT_DIM, c = idx % OUT_DIM;
    const float* r = agg + (size_t)n * F2;
    float sum = r[c] + r[OUT_DIM + c] + r[2 * OUT_DIM + c] + r[3 * OUT_DIM + c];
    out[idx] = 0.25f * sum + bias[c];
}

// ---------------- host ----------------
struct Ptrs {
    float *xl1, *xr1, *agg1, *h, *xl2, *xr2, *agg2;
    float *e1, *a1, *e2, *a2, *s1, *s2;
    unsigned *m1, *m2;
};
static Ptrs P;
static bool g_init = false;

extern "C" void kernel_launch(void* const* d_in, const int* in_sizes, int n_in,
                              void* d_out, int out_size)
{
    if (!g_init) {
        cudaGetSymbolAddress((void**)&P.xl1,  g_xl1);
        cudaGetSymbolAddress((void**)&P.xr1,  g_xr1);
        cudaGetSymbolAddress((void**)&P.agg1, g_agg1);
        cudaGetSymbolAddress((void**)&P.h,    g_h);
        cudaGetSymbolAddress((void**)&P.xl2,  g_xl2);
        cudaGetSymbolAddress((void**)&P.xr2,  g_xr2);
        cudaGetSymbolAddress((void**)&P.agg2, g_agg2);
        cudaGetSymbolAddress((void**)&P.e1,   g_e1);
        cudaGetSymbolAddress((void**)&P.a1,   g_a1);
        cudaGetSymbolAddress((void**)&P.e2,   g_e2);
        cudaGetSymbolAddress((void**)&P.a2,   g_a2);
        cudaGetSymbolAddress((void**)&P.s1,   g_s1);
        cudaGetSymbolAddress((void**)&P.s2,   g_s2);
        cudaGetSymbolAddress((void**)&P.m1,   g_m1);
        cudaGetSymbolAddress((void**)&P.m2,   g_m2);
        g_init = true;
    }

    const float* x     = (const float*)d_in[0];
    const int*   ei    = (const int*)  d_in[1];
    const float* Wl1   = (const float*)d_in[2];
    const float* bl1   = (const float*)d_in[3];
    const float* Wr1   = (const float*)d_in[4];
    const float* br1   = (const float*)d_in[5];
    const float* att1  = (const float*)d_in[6];
    const float* bias1 = (const float*)d_in[7];
    const float* Wl2   = (const float*)d_in[8];
    const float* bl2   = (const float*)d_in[9];
    const float* Wr2   = (const float*)d_in[10];
    const float* br2   = (const float*)d_in[11];
    const float* att2  = (const float*)d_in[12];
    const float* bias2 = (const float*)d_in[13];
    float* out = (float*)d_out;

    const int* esrc = ei;
    const int* edst = ei + EE;

    // init accumulators
    zero_kernel<<<2048, 256>>>(P.agg1, P.agg2, P.m1, P.s1, P.m2, P.s2);

    // layer 1 transforms
    {
        dim3 grid((F1 + 63) / 64, (NN + 63) / 64);
        sgemm_bias_kernel<<<grid, 256>>>(x, Wl1, bl1, P.xl1, NN, IN_DIM, F1);
        sgemm_bias_kernel<<<grid, 256>>>(x, Wr1, br1, P.xr1, NN, IN_DIM, F1);
    }

    const int EDGE_BLOCKS = (ET * 32 + 255) / 256;

    edge_logits1_kernel<<<EDGE_BLOCKS, 256>>>(P.xl1, P.xr1, esrc, edst, att1, P.e1, P.m1);
    exp_sum_kernel<<<(ET * 4 + 255) / 256, 256>>>(P.e1, P.m1, edst, P.a1, P.s1);
    aggregate1_kernel<<<EDGE_BLOCKS, 256>>>(P.xl1, P.a1, P.s1, esrc, edst, P.agg1);
    finalize1_kernel<<<(NN * F1 + 255) / 256, 256>>>(P.agg1, bias1, P.h);

    // layer 2 transforms
    {
        dim3 grid((F2 + 63) / 64, (NN + 63) / 64);
        sgemm_bias_kernel<<<grid, 256>>>(P.h, Wl2, bl2, P.xl2, NN, F1, F2);
        sgemm_bias_kernel<<<grid, 256>>>(P.h, Wr2, br2, P.xr2, NN, F1, F2);
    }

    edge_logits2_kernel<<<EDGE_BLOCKS, 256>>>(P.xl2, P.xr2, esrc, edst, att2, P.e2, P.m2);
    exp_sum_kernel<<<(ET * 4 + 255) / 256, 256>>>(P.e2, P.m2, edst, P.a2, P.s2);
    aggregate2_kernel<<<EDGE_BLOCKS, 256>>>(P.xl2, P.a2, P.s2, esrc, edst, P.agg2);
    finalize2_kernel<<<(NN * OUT_DIM + 255) / 256, 256>>>(P.agg2, bias2, out);
}

// round 2
// speedup vs baseline: 1.1666x; 1.1666x over previous
#include <cuda_runtime.h>
#include <cuda_bf16.h>
#include <cstdint>

// ---------------- problem constants ----------------
#define NN      50000
#define EE      800000
#define ET      (EE + NN)          // 850000 edges incl. self loops
#define IN_DIM  256
#define HID     32
#define HEADS   4
#define OUT_DIM 40
#define F1      (HEADS * HID)      // 128
#define F2      (HEADS * OUT_DIM)  // 160
#define SLOPE   0.2f

// ---------------- scratch (static device memory; no allocs) ----------------
__device__ float g_xc1[(size_t)NN * 2 * F1];   // [xl1 | xr1] per row (256)
__device__ float g_xc2[(size_t)NN * 2 * F2];   // [xl2 | xr2] per row (320)
__device__ float g_h  [(size_t)NN * F1];
__device__ float g_agg1[(size_t)NN * F1];
__device__ float g_agg2[(size_t)NN * F2];
__device__ float g_s1[(size_t)NN * 4];
__device__ float g_s2[(size_t)NN * 4];
__device__ float g_Wc1[(size_t)IN_DIM * 2 * F1];  // 256 x 256
__device__ float g_bc1[2 * F1];
__device__ float g_Wc2[(size_t)F1 * 2 * F2];      // 128 x 320
__device__ float g_bc2[2 * F2];

// ---------------- weight concat: Wc[k][0..Nh)=Wl, [Nh..2Nh)=Wr ----------------
__global__ void concat_w_kernel(const float* __restrict__ Wl, const float* __restrict__ Wr,
                                const float* __restrict__ bl, const float* __restrict__ br,
                                float* __restrict__ Wc, float* __restrict__ bc,
                                int K, int Nh)
{
    int total = K * 2 * Nh;
    for (int idx = blockIdx.x * blockDim.x + threadIdx.x; idx < total;
         idx += gridDim.x * blockDim.x) {
        int k = idx / (2 * Nh);
        int c = idx % (2 * Nh);
        Wc[idx] = (c < Nh) ? Wl[k * Nh + c] : Wr[k * Nh + (c - Nh)];
    }
    int idx = blockIdx.x * blockDim.x + threadIdx.x;
    if (idx < 2 * Nh)
        bc[idx] = (idx < Nh) ? bl[idx] : br[idx - Nh];
}

// ---------------- SGEMM: C[M,Ncol] = A[M,K] @ B[K,Ncol] + bias ----------------
// 128x128 tile, BK=16, 256 threads, 8x8 per thread. K multiple of 16.
__global__ __launch_bounds__(256) void sgemm128_kernel(
    const float* __restrict__ A, const float* __restrict__ B,
    const float* __restrict__ bias, float* __restrict__ C,
    int M, int K, int Ncol)
{
    const int BM = 128, BN = 128, BK = 16;
    __shared__ float As[BK][BM];
    __shared__ float Bs[BK][BN];
    int tid = threadIdx.x;
    int tx = tid & 15, ty = tid >> 4;
    int rowBase = blockIdx.y * BM;
    int colBase = blockIdx.x * BN;

    float acc[8][8] = {};

    for (int k0 = 0; k0 < K; k0 += BK) {
        // A tile: 512 float4, 2 per thread, stored transposed
        #pragma unroll
        for (int i = 0; i < 2; i++) {
            int idx = tid * 2 + i;
            int r  = idx >> 2;         // 0..127
            int kk = (idx & 3) * 4;    // 0,4,8,12
            int grow = rowBase + r;
            float4 v = make_float4(0.f, 0.f, 0.f, 0.f);
            if (grow < M)
                v = *(const float4*)(A + (size_t)grow * K + k0 + kk);
            As[kk + 0][r] = v.x; As[kk + 1][r] = v.y;
            As[kk + 2][r] = v.z; As[kk + 3][r] = v.w;
        }
        // B tile: 512 float4, 2 per thread
        #pragma unroll
        for (int i = 0; i < 2; i++) {
            int idx = tid * 2 + i;
            int r = idx >> 5;          // 0..15
            int c = (idx & 31) * 4;    // 0..124
            int gc = colBase + c;
            float4 v = make_float4(0.f, 0.f, 0.f, 0.f);
            if (gc < Ncol)
                v = *(const float4*)(B + (size_t)(k0 + r) * Ncol + gc);
            *(float4*)&Bs[r][c] = v;
        }
        __syncthreads();

        #pragma unroll
        for (int k = 0; k < BK; k++) {
            float a[8], b[8];
            *(float4*)&a[0] = *(const float4*)&As[k][ty * 8];
            *(float4*)&a[4] = *(const float4*)&As[k][ty * 8 + 4];
            *(float4*)&b[0] = *(const float4*)&Bs[k][tx * 8];
            *(float4*)&b[4] = *(const float4*)&Bs[k][tx * 8 + 4];
            #pragma unroll
            for (int i = 0; i < 8; i++)
                #pragma unroll
                for (int j = 0; j < 8; j++)
                    acc[i][j] += a[i] * b[j];
        }
        __syncthreads();
    }

    // epilogue with bias
    #pragma unroll
    for (int i = 0; i < 8; i++) {
        int grow = rowBase + ty * 8 + i;
        if (grow >= M) continue;
        #pragma unroll
        for (int jv = 0; jv < 2; jv++) {
            int gc = colBase + tx * 8 + jv * 4;
            if (gc < Ncol) {
                float4 bv = *(const float4*)(bias + gc);
                float4 o;
                o.x = acc[i][jv * 4 + 0] + bv.x;
                o.y = acc[i][jv * 4 + 1] + bv.y;
                o.z = acc[i][jv * 4 + 2] + bv.z;
                o.w = acc[i][jv * 4 + 3] + bv.w;
                *(float4*)(C + (size_t)grow * Ncol + gc) = o;
            }
        }
    }
}

// ---------------- fused edge pass, layer 1 (warp/edge, 128 feats) ----------------
// alpha = exp(e)/sum(exp(e)); accumulate numerator + denominator unnormalized.
__global__ __launch_bounds__(256) void edge_pass1_kernel(
    const float* __restrict__ xc,       // [NN, 256] = [xl | xr]
    const int* __restrict__ esrc, const int* __restrict__ edst,
    const float* __restrict__ att,
    float* __restrict__ agg,            // [NN, 128]
    float* __restrict__ ssum)           // [NN, 4]
{
    int warp = (blockIdx.x * blockDim.x + threadIdx.x) >> 5;
    int lane = threadIdx.x & 31;
    if (warp >= ET) return;
    int s, d;
    if (warp < EE) { s = esrc[warp]; d = edst[warp]; }
    else           { s = d = warp - EE; }

    const float* rl = xc + (size_t)s * 256;        // xl[src]
    const float* rr = xc + (size_t)d * 256 + 128;  // xr[dst]

    float4 vl = *(const float4*)(rl + lane * 4);
    float4 vr = *(const float4*)(rr + lane * 4);
    float4 va = *(const float4*)(att + lane * 4);

    float g, sum = 0.f;
    g = vl.x + vr.x; g = g > 0.f ? g : SLOPE * g; sum += g * va.x;
    g = vl.y + vr.y; g = g > 0.f ? g : SLOPE * g; sum += g * va.y;
    g = vl.z + vr.z; g = g > 0.f ? g : SLOPE * g; sum += g * va.z;
    g = vl.w + vr.w; g = g > 0.f ? g : SLOPE * g; sum += g * va.w;

    // reduce within 8-lane head groups; all lanes get their head's logit
    sum += __shfl_xor_sync(0xffffffffu, sum, 1);
    sum += __shfl_xor_sync(0xffffffffu, sum, 2);
    sum += __shfl_xor_sync(0xffffffffu, sum, 4);

    float a = __expf(sum);
    if ((lane & 7) == 0)
        atomicAdd(&ssum[d * 4 + (lane >> 3)], a);

    float* o = agg + (size_t)d * F1 + lane * 4;
    atomicAdd(o + 0, a * vl.x);
    atomicAdd(o + 1, a * vl.y);
    atomicAdd(o + 2, a * vl.z);
    atomicAdd(o + 3, a * vl.w);
}

// ---------------- fused edge pass, layer 2 (warp/edge, 160 feats) ----------------
__global__ __launch_bounds__(256) void edge_pass2_kernel(
    const float* __restrict__ xc,       // [NN, 320] = [xl | xr]
    const int* __restrict__ esrc, const int* __restrict__ edst,
    const float* __restrict__ att,
    float* __restrict__ agg,            // [NN, 160]
    float* __restrict__ ssum)           // [NN, 4]
{
    int warp = (blockIdx.x * blockDim.x + threadIdx.x) >> 5;
    int lane = threadIdx.x & 31;
    if (warp >= ET) return;
    int s, d;
    if (warp < EE) { s = esrc[warp]; d = edst[warp]; }
    else           { s = d = warp - EE; }

    const float* rl = xc + (size_t)s * 320;        // xl[src]
    const float* rr = xc + (size_t)d * 320 + 160;  // xr[dst]

    // lane covers feats [lane*5, lane*5+5); head = lane>>3 (8 lanes * 5 = 40)
    int base = lane * 5;
    float l[5];
    float sum = 0.f;
    #pragma unroll
    for (int i = 0; i < 5; i++) {
        l[i] = rl[base + i];
        float g = l[i] + rr[base + i];
        g = g > 0.f ? g : SLOPE * g;
        sum += g * att[base + i];
    }
    sum += __shfl_xor_sync(0xffffffffu, sum, 1);
    sum += __shfl_xor_sync(0xffffffffu, sum, 2);
    sum += __shfl_xor_sync(0xffffffffu, sum, 4);

    float a = __expf(sum);
    if ((lane & 7) == 0)
        atomicAdd(&ssum[d * 4 + (lane >> 3)], a);

    float* o = agg + (size_t)d * F2 + base;
    #pragma unroll
    for (int i = 0; i < 5; i++)
        atomicAdd(o + i, a * l[i]);
}

// ---------------- finalize layer 1: h = elu(agg/s + bias1) ----------------
__global__ void finalize1_kernel(const float* __restrict__ agg,
                                 const float* __restrict__ ssum,
                                 const float* __restrict__ bias,
                                 float* __restrict__ hout)
{
    int idx = blockIdx.x * blockDim.x + threadIdx.x;
    if (idx >= NN * F1) return;
    int n = idx >> 7, c = idx & 127, h = c >> 5;
    float v = agg[idx] / (ssum[n * 4 + h] + 1e-16f) + bias[c];
    hout[idx] = v > 0.f ? v : (__expf(v) - 1.f);
}

// ---------------- finalize layer 2: out = mean_h(agg/s) + bias2 ----------------
__global__ void finalize2_kernel(const float* __restrict__ agg,
                                 const float* __restrict__ ssum,
                                 const float* __restrict__ bias,
                                 float* __restrict__ out)
{
    int idx = blockIdx.x * blockDim.x + threadIdx.x;
    if (idx >= NN * OUT_DIM) return;
    int n = idx / OUT_DIM, c = idx % OUT_DIM;
    const float* r = agg + (size_t)n * F2;
    const float* sp = ssum + n * 4;
    float sum = 0.f;
    #pragma unroll
    for (int h = 0; h < 4; h++)
        sum += r[h * OUT_DIM + c] / (sp[h] + 1e-16f);
    out[idx] = 0.25f * sum + bias[c];
}

// ---------------- host ----------------
struct Ptrs {
    float *xc1, *xc2, *h, *agg1, *agg2, *s1, *s2;
    float *Wc1, *bc1, *Wc2, *bc2;
};
static Ptrs P;
static bool g_init = false;

extern "C" void kernel_launch(void* const* d_in, const int* in_sizes, int n_in,
                              void* d_out, int out_size)
{
    if (!g_init) {
        cudaGetSymbolAddress((void**)&P.xc1,  g_xc1);
        cudaGetSymbolAddress((void**)&P.xc2,  g_xc2);
        cudaGetSymbolAddress((void**)&P.h,    g_h);
        cudaGetSymbolAddress((void**)&P.agg1, g_agg1);
        cudaGetSymbolAddress((void**)&P.agg2, g_agg2);
        cudaGetSymbolAddress((void**)&P.s1,   g_s1);
        cudaGetSymbolAddress((void**)&P.s2,   g_s2);
        cudaGetSymbolAddress((void**)&P.Wc1,  g_Wc1);
        cudaGetSymbolAddress((void**)&P.bc1,  g_bc1);
        cudaGetSymbolAddress((void**)&P.Wc2,  g_Wc2);
        cudaGetSymbolAddress((void**)&P.bc2,  g_bc2);
        g_init = true;
    }

    const float* x     = (const float*)d_in[0];
    const int*   ei    = (const int*)  d_in[1];
    const float* Wl1   = (const float*)d_in[2];
    const float* bl1   = (const float*)d_in[3];
    const float* Wr1   = (const float*)d_in[4];
    const float* br1   = (const float*)d_in[5];
    const float* att1  = (const float*)d_in[6];
    const float* bias1 = (const float*)d_in[7];
    const float* Wl2   = (const float*)d_in[8];
    const float* bl2   = (const float*)d_in[9];
    const float* Wr2   = (const float*)d_in[10];
    const float* br2   = (const float*)d_in[11];
    const float* att2  = (const float*)d_in[12];
    const float* bias2 = (const float*)d_in[13];
    float* out = (float*)d_out;

    const int* esrc = ei;
    const int* edst = ei + EE;

    // zero accumulators (memset nodes in the graph)
    cudaMemsetAsync(P.agg1, 0, (size_t)NN * F1 * sizeof(float));
    cudaMemsetAsync(P.agg2, 0, (size_t)NN * F2 * sizeof(float));
    cudaMemsetAsync(P.s1,   0, (size_t)NN * 4  * sizeof(float));
    cudaMemsetAsync(P.s2,   0, (size_t)NN * 4  * sizeof(float));

    const int EDGE_BLOCKS = (ET * 32 + 255) / 256;

    // ----- layer 1 -----
    concat_w_kernel<<<256, 256>>>(Wl1, Wr1, bl1, br1, P.Wc1, P.bc1, IN_DIM, F1);
    {
        dim3 grid((2 * F1 + 127) / 128, (NN + 127) / 128);
        sgemm128_kernel<<<grid, 256>>>(x, P.Wc1, P.bc1, P.xc1, NN, IN_DIM, 2 * F1);
    }
    edge_pass1_kernel<<<EDGE_BLOCKS, 256>>>(P.xc1, esrc, edst, att1, P.agg1, P.s1);
    finalize1_kernel<<<(NN * F1 + 255) / 256, 256>>>(P.agg1, P.s1, bias1, P.h);

    // ----- layer 2 -----
    concat_w_kernel<<<256, 256>>>(Wl2, Wr2, bl2, br2, P.Wc2, P.bc2, F1, F2);
    {
        dim3 grid((2 * F2 + 127) / 128, (NN + 127) / 128);
        sgemm128_kernel<<<grid, 256>>>(P.h, P.Wc2, P.bc2, P.xc2, NN, F1, 2 * F2);
    }
    edge_pass2_kernel<<<EDGE_BLOCKS, 256>>>(P.xc2, esrc, edst, att2, P.agg2, P.s2);
    finalize2_kernel<<<(NN * OUT_DIM + 255) / 256, 256>>>(P.agg2, P.s2, bias2, out);
}

// round 3
// speedup vs baseline: 2.8497x; 2.4427x over previous
#include <cuda_runtime.h>
#include <cstdint>

// ---------------- problem constants ----------------
#define NN      50000
#define EE      800000
#define ET      (EE + NN)          // 850000 edges incl. self loops
#define IN_DIM  256
#define HID     32
#define HEADS   4
#define OUT_DIM 40
#define F1      128                // HEADS*HID
#define F2      160                // HEADS*OUT_DIM
#define SLOPE   0.2f

// ---------------- scratch (static device memory; no allocs) ----------------
__device__ float g_xc1[(size_t)NN * 256];   // [xl1 | xr1]
__device__ float g_xc2[(size_t)NN * 320];   // [xl2 | xr2]
__device__ float g_h  [(size_t)NN * F1];
__device__ float g_Wc1[256 * 256];
__device__ float g_bc1[256];
__device__ float g_Wc2[128 * 320];
__device__ float g_bc2[320];
__device__ int   g_deg[NN];
__device__ int   g_rowptr[NN + 1];
__device__ int   g_cursor[NN];
__device__ int   g_csrsrc[ET];

// ---------------- weight concat ----------------
__global__ void concat_w_kernel(const float* __restrict__ Wl, const float* __restrict__ Wr,
                                const float* __restrict__ bl, const float* __restrict__ br,
                                float* __restrict__ Wc, float* __restrict__ bc,
                                int K, int Nh)
{
    int total = K * 2 * Nh;
    for (int idx = blockIdx.x * blockDim.x + threadIdx.x; idx < total;
         idx += gridDim.x * blockDim.x) {
        int k = idx / (2 * Nh);
        int c = idx % (2 * Nh);
        Wc[idx] = (c < Nh) ? Wl[k * Nh + c] : Wr[k * Nh + (c - Nh)];
    }
    int idx = blockIdx.x * blockDim.x + threadIdx.x;
    if (idx < 2 * Nh)
        bc[idx] = (idx < Nh) ? bl[idx] : br[idx - Nh];
}

// ---------------- CSR build ----------------
__global__ void count_kernel(const int* __restrict__ edst)
{
    int idx = blockIdx.x * blockDim.x + threadIdx.x;
    if (idx >= ET) return;
    int d = (idx < EE) ? edst[idx] : idx - EE;
    atomicAdd(&g_deg[d], 1);
}

__global__ void scan_kernel()
{
    __shared__ int ssum[1024];
    int t = threadIdx.x;
    const int CH = (NN + 1023) / 1024;   // 49
    int lo = t * CH;
    int hi = min(lo + CH, NN);
    int s = 0;
    for (int i = lo; i < hi; i++) s += g_deg[i];
    ssum[t] = s;
    __syncthreads();
    for (int off = 1; off < 1024; off <<= 1) {
        int v = (t >= off) ? ssum[t - off] : 0;
        __syncthreads();
        ssum[t] += v;
        __syncthreads();
    }
    int base = (t == 0) ? 0 : ssum[t - 1];
    for (int i = lo; i < hi; i++) {
        g_rowptr[i] = base;
        g_cursor[i] = base;
        base += g_deg[i];
    }
    if (t == 0) g_rowptr[NN] = ET;
}

__global__ void scatter_kernel(const int* __restrict__ esrc, const int* __restrict__ edst)
{
    int idx = blockIdx.x * blockDim.x + threadIdx.x;
    if (idx >= ET) return;
    int s, d;
    if (idx < EE) { s = esrc[idx]; d = edst[idx]; }
    else          { s = d = idx - EE; }
    int pos = atomicAdd(&g_cursor[d], 1);
    g_csrsrc[pos] = s;
}

// ---------------- TF32 tensor-core GEMM ----------------
// C[M,N] = A[M,K] @ B[K,N] + bias. 128x128x16 tile, 256 threads,
// 8 warps as 4x2, warp tile 32x64, mma.m16n8k8.tf32.
__device__ __forceinline__ uint32_t f2tf(float f) {
    uint32_t r;
    asm("cvt.rna.tf32.f32 %0, %1;" : "=r"(r) : "f"(f));
    return r;
}

__global__ __launch_bounds__(256) void gemm_tf32_kernel(
    const float* __restrict__ A, const float* __restrict__ B,
    const float* __restrict__ bias, float* __restrict__ C,
    int M, int K, int N)
{
    __shared__ uint32_t As[16][136];   // [k][m], padded
    __shared__ uint32_t Bs[16][136];   // [k][n], padded
    int tid  = threadIdx.x;
    int lane = tid & 31;
    int warp = tid >> 5;
    int wm = warp & 3;       // 0..3 -> rows of 32
    int wn = warp >> 2;      // 0..1 -> cols of 64
    int rowBase = blockIdx.y * 128;
    int colBase = blockIdx.x * 128;
    int grp = lane >> 2;     // 0..7
    int tig = lane & 3;      // 0..3

    float acc[2][8][4];
    #pragma unroll
    for (int mt = 0; mt < 2; mt++)
        #pragma unroll
        for (int nt = 0; nt < 8; nt++)
            #pragma unroll
            for (int c = 0; c < 4; c++) acc[mt][nt][c] = 0.f;

    for (int k0 = 0; k0 < K; k0 += 16) {
        // A tile: 128 rows x 16 k -> transposed into As[k][m]
        #pragma unroll
        for (int i = 0; i < 2; i++) {
            int idx = tid * 2 + i;
            int r  = idx >> 2;
            int c4 = (idx & 3) * 4;
            int gr = rowBase + r;
            float4 v = make_float4(0.f, 0.f, 0.f, 0.f);
            if (gr < M)
                v = *(const float4*)(A + (size_t)gr * K + k0 + c4);
            As[c4 + 0][r] = f2tf(v.x);
            As[c4 + 1][r] = f2tf(v.y);
            As[c4 + 2][r] = f2tf(v.z);
            As[c4 + 3][r] = f2tf(v.w);
        }
        // B tile: 16 k x 128 n
        #pragma unroll
        for (int i = 0; i < 2; i++) {
            int idx = tid * 2 + i;
            int r = idx >> 5;
            int c = (idx & 31) * 4;
            int gc = colBase + c;
            float4 v = make_float4(0.f, 0.f, 0.f, 0.f);
            if (gc < N)
                v = *(const float4*)(B + (size_t)(k0 + r) * N + gc);
            Bs[r][c + 0] = f2tf(v.x);
            Bs[r][c + 1] = f2tf(v.y);
            Bs[r][c + 2] = f2tf(v.z);
            Bs[r][c + 3] = f2tf(v.w);
        }
        __syncthreads();

        #pragma unroll
        for (int ks = 0; ks < 16; ks += 8) {
            uint32_t af[2][4], bf[8][2];
            #pragma unroll
            for (int mt = 0; mt < 2; mt++) {
                int m = wm * 32 + mt * 16;
                af[mt][0] = As[ks + tig][m + grp];
                af[mt][1] = As[ks + tig][m + grp + 8];
                af[mt][2] = As[ks + tig + 4][m + grp];
                af[mt][3] = As[ks + tig + 4][m + grp + 8];
            }
            #pragma unroll
            for (int nt = 0; nt < 8; nt++) {
                int nb = wn * 64 + nt * 8;
                bf[nt][0] = Bs[ks + tig][nb + grp];
                bf[nt][1] = Bs[ks + tig + 4][nb + grp];
            }
            #pragma unroll
            for (int mt = 0; mt < 2; mt++)
                #pragma unroll
                for (int nt = 0; nt < 8; nt++) {
                    asm volatile(
                        "mma.sync.aligned.m16n8k8.row.col.f32.tf32.tf32.f32 "
                        "{%0,%1,%2,%3}, {%4,%5,%6,%7}, {%8,%9}, {%0,%1,%2,%3};"
                        : "+f"(acc[mt][nt][0]), "+f"(acc[mt][nt][1]),
                          "+f"(acc[mt][nt][2]), "+f"(acc[mt][nt][3])
                        : "r"(af[mt][0]), "r"(af[mt][1]), "r"(af[mt][2]), "r"(af[mt][3]),
                          "r"(bf[nt][0]), "r"(bf[nt][1]));
                }
        }
        __syncthreads();
    }

    // epilogue
    #pragma unroll
    for (int mt = 0; mt < 2; mt++) {
        #pragma unroll
        for (int nt = 0; nt < 8; nt++) {
            int row0 = rowBase + wm * 32 + mt * 16 + grp;
            int col0 = colBase + wn * 64 + nt * 8 + tig * 2;
            if (col0 < N) {
                float b0 = bias[col0];
                float b1 = (col0 + 1 < N) ? bias[col0 + 1] : 0.f;
                if (row0 < M) {
                    C[(size_t)row0 * N + col0] = acc[mt][nt][0] + b0;
                    if (col0 + 1 < N)
                        C[(size_t)row0 * N + col0 + 1] = acc[mt][nt][1] + b1;
                }
                if (row0 + 8 < M) {
                    C[(size_t)(row0 + 8) * N + col0] = acc[mt][nt][2] + b0;
                    if (col0 + 1 < N)
                        C[(size_t)(row0 + 8) * N + col0 + 1] = acc[mt][nt][3] + b1;
                }
            }
        }
    }
}

// ---------------- layer 1: warp per node, full fused softmax+agg+ELU ----------------
__global__ __launch_bounds__(256) void agg1_kernel(const float* __restrict__ att,
                                                   const float* __restrict__ bias)
{
    int node = (blockIdx.x * blockDim.x + threadIdx.x) >> 5;
    int lane = threadIdx.x & 31;
    if (node >= NN) return;

    float4 vr = *(const float4*)(g_xc1 + (size_t)node * 256 + 128 + lane * 4);
    float4 va = *(const float4*)(att + lane * 4);

    float ax = 0.f, ay = 0.f, az = 0.f, aw = 0.f, ssum = 0.f;

    int i   = g_rowptr[node];
    int end = g_rowptr[node + 1];
    int s = g_csrsrc[i];
    float4 vl = *(const float4*)(g_xc1 + (size_t)s * 256 + lane * 4);

    while (i < end) {
        i++;
        float4 vln;
        if (i < end) {
            int sn = g_csrsrc[i];
            vln = *(const float4*)(g_xc1 + (size_t)sn * 256 + lane * 4);
        }
        float g, sum = 0.f;
        g = vl.x + vr.x; g = g > 0.f ? g : SLOPE * g; sum += g * va.x;
        g = vl.y + vr.y; g = g > 0.f ? g : SLOPE * g; sum += g * va.y;
        g = vl.z + vr.z; g = g > 0.f ? g : SLOPE * g; sum += g * va.z;
        g = vl.w + vr.w; g = g > 0.f ? g : SLOPE * g; sum += g * va.w;
        sum += __shfl_xor_sync(0xffffffffu, sum, 1);
        sum += __shfl_xor_sync(0xffffffffu, sum, 2);
        sum += __shfl_xor_sync(0xffffffffu, sum, 4);
        float a = __expf(sum);
        ax += a * vl.x; ay += a * vl.y; az += a * vl.z; aw += a * vl.w;
        ssum += a;
        vl = vln;
    }

    float inv = 1.f / (ssum + 1e-16f);
    float4 bv = *(const float4*)(bias + lane * 4);
    float4 o;
    o.x = ax * inv + bv.x;
    o.y = ay * inv + bv.y;
    o.z = az * inv + bv.z;
    o.w = aw * inv + bv.w;
    o.x = o.x > 0.f ? o.x : (__expf(o.x) - 1.f);
    o.y = o.y > 0.f ? o.y : (__expf(o.y) - 1.f);
    o.z = o.z > 0.f ? o.z : (__expf(o.z) - 1.f);
    o.w = o.w > 0.f ? o.w : (__expf(o.w) - 1.f);
    *(float4*)(g_h + (size_t)node * F1 + lane * 4) = o;
}

// ---------------- layer 2: warp per node, fused softmax+agg+head-mean+bias ----------------
__global__ __launch_bounds__(256) void agg2_kernel(const float* __restrict__ att,
                                                   const float* __restrict__ bias,
                                                   float* __restrict__ out)
{
    int node = (blockIdx.x * blockDim.x + threadIdx.x) >> 5;
    int lane = threadIdx.x & 31;
    if (node >= NN) return;

    int base = lane * 5;   // head = lane>>3, within-head offset = (lane&7)*5
    float vr[5], va[5];
    #pragma unroll
    for (int j = 0; j < 5; j++) {
        vr[j] = g_xc2[(size_t)node * 320 + 160 + base + j];
        va[j] = att[base + j];
    }

    float acc[5] = {0.f, 0.f, 0.f, 0.f, 0.f};
    float ssum = 0.f;

    int i   = g_rowptr[node];
    int end = g_rowptr[node + 1];
    int s = g_csrsrc[i];
    float vl[5];
    #pragma unroll
    for (int j = 0; j < 5; j++) vl[j] = g_xc2[(size_t)s * 320 + base + j];

    while (i < end) {
        i++;
        float vln[5];
        if (i < end) {
            int sn = g_csrsrc[i];
            #pragma unroll
            for (int j = 0; j < 5; j++) vln[j] = g_xc2[(size_t)sn * 320 + base + j];
        }
        float sum = 0.f;
        #pragma unroll
        for (int j = 0; j < 5; j++) {
            float g = vl[j] + vr[j];
            g = g > 0.f ? g : SLOPE * g;
            sum += g * va[j];
        }
        sum += __shfl_xor_sync(0xffffffffu, sum, 1);
        sum += __shfl_xor_sync(0xffffffffu, sum, 2);
        sum += __shfl_xor_sync(0xffffffffu, sum, 4);
        float a = __expf(sum);
        #pragma unroll
        for (int j = 0; j < 5; j++) acc[j] += a * vl[j];
        ssum += a;
        #pragma unroll
        for (int j = 0; j < 5; j++) vl[j] = vln[j];
    }

    float inv = 1.f / (ssum + 1e-16f);
    float v[5];
    #pragma unroll
    for (int j = 0; j < 5; j++) {
        v[j] = acc[j] * inv;
        v[j] += __shfl_xor_sync(0xffffffffu, v[j], 8);
        v[j] += __shfl_xor_sync(0xffffffffu, v[j], 16);
        v[j] *= 0.25f;
    }
    if (lane < 8) {
        #pragma unroll
        for (int j = 0; j < 5; j++)
            out[(size_t)node * OUT_DIM + base + j] = v[j] + bias[base + j];
    }
}

// ---------------- host ----------------
struct Ptrs {
    float *xc1, *xc2, *h, *Wc1, *bc1, *Wc2, *bc2;
    int *deg;
};
static Ptrs P;
static bool g_init = false;

extern "C" void kernel_launch(void* const* d_in, const int* in_sizes, int n_in,
                              void* d_out, int out_size)
{
    if (!g_init) {
        cudaGetSymbolAddress((void**)&P.xc1, g_xc1);
        cudaGetSymbolAddress((void**)&P.xc2, g_xc2);
        cudaGetSymbolAddress((void**)&P.h,   g_h);
        cudaGetSymbolAddress((void**)&P.Wc1, g_Wc1);
        cudaGetSymbolAddress((void**)&P.bc1, g_bc1);
        cudaGetSymbolAddress((void**)&P.Wc2, g_Wc2);
        cudaGetSymbolAddress((void**)&P.bc2, g_bc2);
        cudaGetSymbolAddress((void**)&P.deg, g_deg);
        g_init = true;
    }

    const float* x     = (const float*)d_in[0];
    const int*   ei    = (const int*)  d_in[1];
    const float* Wl1   = (const float*)d_in[2];
    const float* bl1   = (const float*)d_in[3];
    const float* Wr1   = (const float*)d_in[4];
    const float* br1   = (const float*)d_in[5];
    const float* att1  = (const float*)d_in[6];
    const float* bias1 = (const float*)d_in[7];
    const float* Wl2   = (const float*)d_in[8];
    const float* bl2   = (const float*)d_in[9];
    const float* Wr2   = (const float*)d_in[10];
    const float* br2   = (const float*)d_in[11];
    const float* att2  = (const float*)d_in[12];
    const float* bias2 = (const float*)d_in[13];
    float* out = (float*)d_out;

    const int* esrc = ei;
    const int* edst = ei + EE;

    // CSR build
    cudaMemsetAsync(P.deg, 0, NN * sizeof(int));
    count_kernel<<<(ET + 255) / 256, 256>>>(edst);
    scan_kernel<<<1, 1024>>>();
    scatter_kernel<<<(ET + 255) / 256, 256>>>(esrc, edst);

    // ----- layer 1 -----
    concat_w_kernel<<<256, 256>>>(Wl1, Wr1, bl1, br1, P.Wc1, P.bc1, IN_DIM, F1);
    {
        dim3 grid(2, (NN + 127) / 128);
        gemm_tf32_kernel<<<grid, 256>>>(x, P.Wc1, P.bc1, P.xc1, NN, IN_DIM, 256);
    }
    agg1_kernel<<<(NN * 32 + 255) / 256, 256>>>(att1, bias1);

    // ----- layer 2 -----
    concat_w_kernel<<<256, 256>>>(Wl2, Wr2, bl2, br2, P.Wc2, P.bc2, F1, F2);
    {
        dim3 grid(3, (NN + 127) / 128);
        gemm_tf32_kernel<<<grid, 256>>>(P.h, P.Wc2, P.bc2, P.xc2, NN, F1, 320);
    }
    agg2_kernel<<<(NN * 32 + 255) / 256, 256>>>(att2, bias2, out);
}

// round 4
// speedup vs baseline: 3.1502x; 1.1055x over previous
#include <cuda_runtime.h>
#include <cstdint>

#define NN      50000
#define EE      800000
#define ET      (EE + NN)
#define IN_DIM  256
#define HID     32
#define HEADS   4
#define OUT_DIM 40
#define F1      128
#define F2      160
#define SLOPE   0.2f
#define FULLMASK 0xffffffffu

// ---------------- scratch ----------------
__device__ float g_xc1[(size_t)NN * 256];   // [xl1 | xr1]
__device__ float g_xc2[(size_t)NN * 320];   // [xl2 | xr2]
__device__ float g_h  [(size_t)NN * F1];
__device__ int   g_deg[NN];
__device__ int   g_rowptr[NN + 1];
__device__ int   g_cursor[NN];
__device__ int   g_csrsrc[ET];

// ---------------- CSR build ----------------
__global__ void count_kernel(const int* __restrict__ edst)
{
    int idx = blockIdx.x * blockDim.x + threadIdx.x;
    if (idx >= ET) return;
    int d = (idx < EE) ? edst[idx] : idx - EE;
    atomicAdd(&g_deg[d], 1);
}

__global__ void scan_kernel()
{
    __shared__ int ssum[1024];
    int t = threadIdx.x;
    const int CH = (NN + 1023) / 1024;
    int lo = t * CH;
    int hi = min(lo + CH, NN);
    int s = 0;
    for (int i = lo; i < hi; i++) s += g_deg[i];
    ssum[t] = s;
    __syncthreads();
    for (int off = 1; off < 1024; off <<= 1) {
        int v = (t >= off) ? ssum[t - off] : 0;
        __syncthreads();
        ssum[t] += v;
        __syncthreads();
    }
    int base = (t == 0) ? 0 : ssum[t - 1];
    for (int i = lo; i < hi; i++) {
        g_rowptr[i] = base;
        g_cursor[i] = base;
        base += g_deg[i];
    }
    if (t == 0) g_rowptr[NN] = ET;
}

__global__ void scatter_kernel(const int* __restrict__ esrc, const int* __restrict__ edst)
{
    int idx = blockIdx.x * blockDim.x + threadIdx.x;
    if (idx >= ET) return;
    int s, d;
    if (idx < EE) { s = esrc[idx]; d = edst[idx]; }
    else          { s = d = idx - EE; }
    int pos = atomicAdd(&g_cursor[d], 1);
    g_csrsrc[pos] = s;
}

// ---------------- TF32 GEMM, double-buffered, fused Wl|Wr concat + bias ----------------
__device__ __forceinline__ uint32_t f2tf(float f) {
    uint32_t r;
    asm("cvt.rna.tf32.f32 %0, %1;" : "=r"(r) : "f"(f));
    return r;
}
__device__ __forceinline__ void cpa16(uint32_t d, const void* s, int sz) {
    asm volatile("cp.async.cg.shared.global [%0], [%1], 16, %2;"
                 :: "r"(d), "l"(s), "r"(sz));
}

// C[M, 2*Nh] = A[M,K] @ [Wl | Wr] + [bl | br]
__global__ __launch_bounds__(256, 2) void gemm_tf32_fused(
    const float* __restrict__ A, const float* __restrict__ Wl,
    const float* __restrict__ Wr, const float* __restrict__ bl,
    const float* __restrict__ br, float* __restrict__ C,
    int M, int K, int Nh)
{
    const int N = 2 * Nh;
    __shared__ uint32_t As[2][16][136];
    __shared__ float    Bs[2][16][136];
    int tid = threadIdx.x, lane = tid & 31, warp = tid >> 5;
    int wm = warp & 3, wn = warp >> 2;
    int rowBase = blockIdx.y * 128, colBase = blockIdx.x * 128;
    int grp = lane >> 2, tig = lane & 3;

    float acc[2][8][4];
    #pragma unroll
    for (int mt = 0; mt < 2; mt++)
        #pragma unroll
        for (int nt = 0; nt < 8; nt++)
            #pragma unroll
            for (int c = 0; c < 4; c++) acc[mt][nt][c] = 0.f;

    int nIter = K >> 4;

    float4 pa, pb;
    // prologue: tile 0
    {
        int gr = rowBase + (tid >> 1);
        int kc = (tid & 1) * 8;
        pa = make_float4(0.f, 0.f, 0.f, 0.f); pb = pa;
        if (gr < M) {
            pa = *(const float4*)(A + (size_t)gr * K + kc);
            pb = *(const float4*)(A + (size_t)gr * K + kc + 4);
        }
    }
    {
        int rB = tid >> 4;
        int cB = (tid & 15) * 8;
        #pragma unroll
        for (int i = 0; i < 2; i++) {
            int gc = colBase + cB + i * 4;
            const float* src = Wl; int sz = 0;
            if (gc < Nh)      { src = Wl + (size_t)rB * Nh + gc;        sz = 16; }
            else if (gc < N)  { src = Wr + (size_t)rB * Nh + (gc - Nh); sz = 16; }
            cpa16((uint32_t)__cvta_generic_to_shared(&Bs[0][rB][cB + i * 4]), src, sz);
        }
    }
    {
        int r = tid >> 1, c4 = (tid & 1) * 8;
        As[0][c4 + 0][r] = f2tf(pa.x); As[0][c4 + 1][r] = f2tf(pa.y);
        As[0][c4 + 2][r] = f2tf(pa.z); As[0][c4 + 3][r] = f2tf(pa.w);
        As[0][c4 + 4][r] = f2tf(pb.x); As[0][c4 + 5][r] = f2tf(pb.y);
        As[0][c4 + 6][r] = f2tf(pb.z); As[0][c4 + 7][r] = f2tf(pb.w);
    }
    asm volatile("cp.async.commit_group;");

    int buf = 0;
    for (int it = 0; it < nIter; it++) {
        asm volatile("cp.async.wait_group 0;");
        __syncthreads();
        bool more = (it + 1 < nIter);
        if (more) {
            int k0 = (it + 1) << 4;
            int gr = rowBase + (tid >> 1);
            int kc = k0 + (tid & 1) * 8;
            pa = make_float4(0.f, 0.f, 0.f, 0.f); pb = pa;
            if (gr < M) {
                pa = *(const float4*)(A + (size_t)gr * K + kc);
                pb = *(const float4*)(A + (size_t)gr * K + kc + 4);
            }
            int rB = tid >> 4;
            int cB = (tid & 15) * 8;
            #pragma unroll
            for (int i = 0; i < 2; i++) {
                int gc = colBase + cB + i * 4;
                const float* src = Wl; int sz = 0;
                if (gc < Nh)      { src = Wl + (size_t)(k0 + rB) * Nh + gc;        sz = 16; }
                else if (gc < N)  { src = Wr + (size_t)(k0 + rB) * Nh + (gc - Nh); sz = 16; }
                cpa16((uint32_t)__cvta_generic_to_shared(&Bs[buf ^ 1][rB][cB + i * 4]), src, sz);
            }
            asm volatile("cp.async.commit_group;");
        }

        #pragma unroll
        for (int ks = 0; ks < 16; ks += 8) {
            uint32_t af[2][4], bf[8][2];
            #pragma unroll
            for (int mt = 0; mt < 2; mt++) {
                int m = wm * 32 + mt * 16;
                af[mt][0] = As[buf][ks + tig][m + grp];
                af[mt][1] = As[buf][ks + tig][m + grp + 8];
                af[mt][2] = As[buf][ks + tig + 4][m + grp];
                af[mt][3] = As[buf][ks + tig + 4][m + grp + 8];
            }
            #pragma unroll
            for (int nt = 0; nt < 8; nt++) {
                int nb = wn * 64 + nt * 8;
                bf[nt][0] = f2tf(Bs[buf][ks + tig][nb + grp]);
                bf[nt][1] = f2tf(Bs[buf][ks + tig + 4][nb + grp]);
            }
            #pragma unroll
            for (int mt = 0; mt < 2; mt++)
                #pragma unroll
                for (int nt = 0; nt < 8; nt++) {
                    asm volatile(
                        "mma.sync.aligned.m16n8k8.row.col.f32.tf32.tf32.f32 "
                        "{%0,%1,%2,%3}, {%4,%5,%6,%7}, {%8,%9}, {%0,%1,%2,%3};"
                        : "+f"(acc[mt][nt][0]), "+f"(acc[mt][nt][1]),
                          "+f"(acc[mt][nt][2]), "+f"(acc[mt][nt][3])
                        : "r"(af[mt][0]), "r"(af[mt][1]), "r"(af[mt][2]), "r"(af[mt][3]),
                          "r"(bf[nt][0]), "r"(bf[nt][1]));
                }
        }

        if (more) {
            int r = tid >> 1, c4 = (tid & 1) * 8;
            int b = buf ^ 1;
            As[b][c4 + 0][r] = f2tf(pa.x); As[b][c4 + 1][r] = f2tf(pa.y);
            As[b][c4 + 2][r] = f2tf(pa.z); As[b][c4 + 3][r] = f2tf(pa.w);
            As[b][c4 + 4][r] = f2tf(pb.x); As[b][c4 + 5][r] = f2tf(pb.y);
            As[b][c4 + 6][r] = f2tf(pb.z); As[b][c4 + 7][r] = f2tf(pb.w);
        }
        buf ^= 1;
    }

    // epilogue: fused bias from bl/br
    #pragma unroll
    for (int mt = 0; mt < 2; mt++) {
        #pragma unroll
        for (int nt = 0; nt < 8; nt++) {
            int row0 = rowBase + wm * 32 + mt * 16 + grp;
            int col0 = colBase + wn * 64 + nt * 8 + tig * 2;
            if (col0 < N) {
                float b0 = (col0     < Nh) ? bl[col0]     : br[col0 - Nh];
                float b1 = (col0 + 1 < Nh) ? bl[col0 + 1] : br[col0 + 1 - Nh];
                if (row0 < M) {
                    float2 o = make_float2(acc[mt][nt][0] + b0, acc[mt][nt][1] + b1);
                    *(float2*)(C + (size_t)row0 * N + col0) = o;
                }
                if (row0 + 8 < M) {
                    float2 o = make_float2(acc[mt][nt][2] + b0, acc[mt][nt][3] + b1);
                    *(float2*)(C + (size_t)(row0 + 8) * N + col0) = o;
                }
            }
        }
    }
}

// ---------------- layer 1 agg: warp/node, half-warp/edge, prefetch ----------------
__global__ __launch_bounds__(256) void agg1_kernel(
    const float* __restrict__ xc, const int* __restrict__ rowptr,
    const int* __restrict__ csrsrc, const float* __restrict__ att,
    const float* __restrict__ bias, float* __restrict__ hout)
{
    int node = (blockIdx.x * blockDim.x + threadIdx.x) >> 5;
    int lane = threadIdx.x & 31;
    if (node >= NN) return;
    int sub = lane >> 4, l = lane & 15;

    const float* vp = xc + (size_t)node * 256 + 128 + l * 8;
    float4 vr0 = *(const float4*)(vp);
    float4 vr1 = *(const float4*)(vp + 4);
    float4 va0 = *(const float4*)(att + l * 8);
    float4 va1 = *(const float4*)(att + l * 8 + 4);

    int beg = rowptr[node], end = rowptr[node + 1];
    int deg = end - beg;
    int iters = (deg + 1) >> 1;

    float4 acc0 = make_float4(0.f, 0.f, 0.f, 0.f);
    float4 acc1 = make_float4(0.f, 0.f, 0.f, 0.f);
    float ssum = 0.f;

    int idx = beg + sub;
    bool v = idx < end;
    int s = v ? csrsrc[idx] : csrsrc[beg];
    const float* sp = xc + (size_t)s * 256 + l * 8;
    float4 c0 = *(const float4*)sp;
    float4 c1 = *(const float4*)(sp + 4);

    for (int it = 0; it < iters; it++) {
        int idxn = idx + 2;
        bool vn = idxn < end;
        int sn = vn ? csrsrc[idxn] : csrsrc[beg];
        const float* np = xc + (size_t)sn * 256 + l * 8;
        float4 n0 = *(const float4*)np;
        float4 n1 = *(const float4*)(np + 4);

        float g, sum = 0.f;
        g = c0.x + vr0.x; g = g > 0.f ? g : SLOPE * g; sum += g * va0.x;
        g = c0.y + vr0.y; g = g > 0.f ? g : SLOPE * g; sum += g * va0.y;
        g = c0.z + vr0.z; g = g > 0.f ? g : SLOPE * g; sum += g * va0.z;
        g = c0.w + vr0.w; g = g > 0.f ? g : SLOPE * g; sum += g * va0.w;
        g = c1.x + vr1.x; g = g > 0.f ? g : SLOPE * g; sum += g * va1.x;
        g = c1.y + vr1.y; g = g > 0.f ? g : SLOPE * g; sum += g * va1.y;
        g = c1.z + vr1.z; g = g > 0.f ? g : SLOPE * g; sum += g * va1.z;
        g = c1.w + vr1.w; g = g > 0.f ? g : SLOPE * g; sum += g * va1.w;
        sum += __shfl_xor_sync(FULLMASK, sum, 1);
        sum += __shfl_xor_sync(FULLMASK, sum, 2);
        float a = v ? __expf(sum) : 0.f;
        acc0.x += a * c0.x; acc0.y += a * c0.y; acc0.z += a * c0.z; acc0.w += a * c0.w;
        acc1.x += a * c1.x; acc1.y += a * c1.y; acc1.z += a * c1.z; acc1.w += a * c1.w;
        ssum += a;
        c0 = n0; c1 = n1; v = vn; idx = idxn;
    }

    acc0.x += __shfl_xor_sync(FULLMASK, acc0.x, 16);
    acc0.y += __shfl_xor_sync(FULLMASK, acc0.y, 16);
    acc0.z += __shfl_xor_sync(FULLMASK, acc0.z, 16);
    acc0.w += __shfl_xor_sync(FULLMASK, acc0.w, 16);
    acc1.x += __shfl_xor_sync(FULLMASK, acc1.x, 16);
    acc1.y += __shfl_xor_sync(FULLMASK, acc1.y, 16);
    acc1.z += __shfl_xor_sync(FULLMASK, acc1.z, 16);
    acc1.w += __shfl_xor_sync(FULLMASK, acc1.w, 16);
    ssum   += __shfl_xor_sync(FULLMASK, ssum,   16);

    if (sub == 0) {
        float inv = 1.f / (ssum + 1e-16f);
        float4 b0 = *(const float4*)(bias + l * 8);
        float4 b1 = *(const float4*)(bias + l * 8 + 4);
        float4 o0, o1;
        o0.x = acc0.x * inv + b0.x; o0.y = acc0.y * inv + b0.y;
        o0.z = acc0.z * inv + b0.z; o0.w = acc0.w * inv + b0.w;
        o1.x = acc1.x * inv + b1.x; o1.y = acc1.y * inv + b1.y;
        o1.z = acc1.z * inv + b1.z; o1.w = acc1.w * inv + b1.w;
        o0.x = o0.x > 0.f ? o0.x : (__expf(o0.x) - 1.f);
        o0.y = o0.y > 0.f ? o0.y : (__expf(o0.y) - 1.f);
        o0.z = o0.z > 0.f ? o0.z : (__expf(o0.z) - 1.f);
        o0.w = o0.w > 0.f ? o0.w : (__expf(o0.w) - 1.f);
        o1.x = o1.x > 0.f ? o1.x : (__expf(o1.x) - 1.f);
        o1.y = o1.y > 0.f ? o1.y : (__expf(o1.y) - 1.f);
        o1.z = o1.z > 0.f ? o1.z : (__expf(o1.z) - 1.f);
        o1.w = o1.w > 0.f ? o1.w : (__expf(o1.w) - 1.f);
        *(float4*)(hout + (size_t)node * F1 + l * 8)     = o0;
        *(float4*)(hout + (size_t)node * F1 + l * 8 + 4) = o1;
    }
}

// ---------------- layer 2 agg: warp/node, half-warp/edge, prefetch ----------------
__global__ __launch_bounds__(256) void agg2_kernel(
    const float* __restrict__ xc, const int* __restrict__ rowptr,
    const int* __restrict__ csrsrc, const float* __restrict__ att,
    const float* __restrict__ bias, float* __restrict__ out)
{
    int node = (blockIdx.x * blockDim.x + threadIdx.x) >> 5;
    int lane = threadIdx.x & 31;
    if (node >= NN) return;
    int sub = lane >> 4, l = lane & 15;
    int base = l * 10;   // head = l>>2, 4 lanes * 10 feats = 40 per head

    float2 vr[5], va[5];
    const float* vp = xc + (size_t)node * 320 + 160 + base;
    #pragma unroll
    for (int j = 0; j < 5; j++) {
        vr[j] = *(const float2*)(vp + 2 * j);
        va[j] = *(const float2*)(att + base + 2 * j);
    }

    int beg = rowptr[node], end = rowptr[node + 1];
    int deg = end - beg;
    int iters = (deg + 1) >> 1;

    float2 acc[5];
    #pragma unroll
    for (int j = 0; j < 5; j++) acc[j] = make_float2(0.f, 0.f);
    float ssum = 0.f;

    int idx = beg + sub;
    bool v = idx < end;
    int s = v ? csrsrc[idx] : csrsrc[beg];
    float2 cur[5];
    {
        const float* sp = xc + (size_t)s * 320 + base;
        #pragma unroll
        for (int j = 0; j < 5; j++) cur[j] = *(const float2*)(sp + 2 * j);
    }

    for (int it = 0; it < iters; it++) {
        int idxn = idx + 2;
        bool vn = idxn < end;
        int sn = vn ? csrsrc[idxn] : csrsrc[beg];
        float2 nxt[5];
        {
            const float* sp = xc + (size_t)sn * 320 + base;
            #pragma unroll
            for (int j = 0; j < 5; j++) nxt[j] = *(const float2*)(sp + 2 * j);
        }
        float sum = 0.f;
        #pragma unroll
        for (int j = 0; j < 5; j++) {
            float g = cur[j].x + vr[j].x; g = g > 0.f ? g : SLOPE * g; sum += g * va[j].x;
            g       = cur[j].y + vr[j].y; g = g > 0.f ? g : SLOPE * g; sum += g * va[j].y;
        }
        sum += __shfl_xor_sync(FULLMASK, sum, 1);
        sum += __shfl_xor_sync(FULLMASK, sum, 2);
        float a = v ? __expf(sum) : 0.f;
        #pragma unroll
        for (int j = 0; j < 5; j++) { acc[j].x += a * cur[j].x; acc[j].y += a * cur[j].y; }
        ssum += a;
        #pragma unroll
        for (int j = 0; j < 5; j++) cur[j] = nxt[j];
        v = vn; idx = idxn;
    }

    #pragma unroll
    for (int j = 0; j < 5; j++) {
        acc[j].x += __shfl_xor_sync(FULLMASK, acc[j].x, 16);
        acc[j].y += __shfl_xor_sync(FULLMASK, acc[j].y, 16);
    }
    ssum += __shfl_xor_sync(FULLMASK, ssum, 16);

    float inv = 1.f / (ssum + 1e-16f);
    #pragma unroll
    for (int j = 0; j < 5; j++) {
        float vx = acc[j].x * inv, vy = acc[j].y * inv;
        vx += __shfl_xor_sync(FULLMASK, vx, 4);
        vx += __shfl_xor_sync(FULLMASK, vx, 8);
        vy += __shfl_xor_sync(FULLMASK, vy, 4);
        vy += __shfl_xor_sync(FULLMASK, vy, 8);
        acc[j].x = vx; acc[j].y = vy;
    }

    if (sub == 0 && l < 4) {
        #pragma unroll
        for (int j = 0; j < 5; j++) {
            float2 o;
            o.x = 0.25f * acc[j].x + bias[base + 2 * j];
            o.y = 0.25f * acc[j].y + bias[base + 2 * j + 1];
            *(float2*)(out + (size_t)node * OUT_DIM + base + 2 * j) = o;
        }
    }
}

// ---------------- host ----------------
struct Ptrs {
    float *xc1, *xc2, *h;
    int *deg, *rowptr, *csrsrc;
};
static Ptrs P;
static bool g_init = false;

extern "C" void kernel_launch(void* const* d_in, const int* in_sizes, int n_in,
                              void* d_out, int out_size)
{
    if (!g_init) {
        cudaGetSymbolAddress((void**)&P.xc1,    g_xc1);
        cudaGetSymbolAddress((void**)&P.xc2,    g_xc2);
        cudaGetSymbolAddress((void**)&P.h,      g_h);
        cudaGetSymbolAddress((void**)&P.deg,    g_deg);
        cudaGetSymbolAddress((void**)&P.rowptr, g_rowptr);
        cudaGetSymbolAddress((void**)&P.csrsrc, g_csrsrc);
        g_init = true;
    }

    const float* x     = (const float*)d_in[0];
    const int*   ei    = (const int*)  d_in[1];
    const float* Wl1   = (const float*)d_in[2];
    const float* bl1   = (const float*)d_in[3];
    const float* Wr1   = (const float*)d_in[4];
    const float* br1   = (const float*)d_in[5];
    const float* att1  = (const float*)d_in[6];
    const float* bias1 = (const float*)d_in[7];
    const float* Wl2   = (const float*)d_in[8];
    const float* bl2   = (const float*)d_in[9];
    const float* Wr2   = (const float*)d_in[10];
    const float* br2   = (const float*)d_in[11];
    const float* att2  = (const float*)d_in[12];
    const float* bias2 = (const float*)d_in[13];
    float* out = (float*)d_out;

    const int* esrc = ei;
    const int* edst = ei + EE;

    // CSR build
    cudaMemsetAsync(P.deg, 0, NN * sizeof(int));
    count_kernel<<<(ET + 255) / 256, 256>>>(edst);
    scan_kernel<<<1, 1024>>>();
    scatter_kernel<<<(ET + 255) / 256, 256>>>(esrc, edst);

    // ----- layer 1 -----
    {
        dim3 grid(2, (NN + 127) / 128);
        gemm_tf32_fused<<<grid, 256>>>(x, Wl1, Wr1, bl1, br1, P.xc1, NN, IN_DIM, F1);
    }
    agg1_kernel<<<(NN * 32 + 255) / 256, 256>>>(P.xc1, P.rowptr, P.csrsrc, att1, bias1, P.h);

    // ----- layer 2 -----
    {
        dim3 grid(3, (NN + 127) / 128);
        gemm_tf32_fused<<<grid, 256>>>(P.h, Wl2, Wr2, bl2, br2, P.xc2, NN, F1, F2);
    }
    agg2_kernel<<<(NN * 32 + 255) / 256, 256>>>(P.xc2, P.rowptr, P.csrsrc, att2, bias2, out);
}